// round 1
// baseline (speedup 1.0000x reference)
#include <cuda_runtime.h>
#include <cstdint>
#include <math.h>

// Problem constants (fixed by the reference: B=8, SQ=SK=4096, D=64)
#define B_   8
#define SQ_  4096
#define SK_  4096
#define D_   64

// Tiling
#define BQ   128          // q rows per CTA
#define BK   64           // keys per tile
#define NWARP 8
#define NTHREADS 256
#define KSTRIDE 68        // padded floats per smem row (64 + 4)
#define PSTRIDE 68

// smem (floats): K double buf | V double buf | P per warp
#define KBUF_FLOATS (2 * BK * KSTRIDE)            // 8704
#define VBUF_FLOATS (2 * BK * KSTRIDE)            // 8704
#define PBUF_FLOATS (NWARP * 16 * PSTRIDE)        // 8704
#define SMEM_FLOATS (KBUF_FLOATS + VBUF_FLOATS + PBUF_FLOATS)
#define SMEM_BYTES  (SMEM_FLOATS * 4)             // 104448

__device__ __forceinline__ uint32_t f2tf32(float f) {
    uint32_t u;
    asm("cvt.rna.tf32.f32 %0, %1;" : "=r"(u) : "f"(f));
    return u;
}

__device__ __forceinline__ float fast_exp2(float x) {
    float y;
    asm("ex2.approx.ftz.f32 %0, %1;" : "=f"(y) : "f"(x));
    return y;
}

__device__ __forceinline__ void mma_tf32(float& d0, float& d1, float& d2, float& d3,
                                         uint32_t a0, uint32_t a1, uint32_t a2, uint32_t a3,
                                         uint32_t b0, uint32_t b1) {
    asm volatile(
        "mma.sync.aligned.m16n8k8.row.col.f32.tf32.tf32.f32 "
        "{%0,%1,%2,%3}, {%4,%5,%6,%7}, {%8,%9}, {%0,%1,%2,%3};"
        : "+f"(d0), "+f"(d1), "+f"(d2), "+f"(d3)
        : "r"(a0), "r"(a1), "r"(a2), "r"(a3), "r"(b0), "r"(b1));
}

__device__ __forceinline__ void cp_async16(uint32_t dst_smem, const void* src) {
    asm volatile("cp.async.cg.shared.global [%0], [%1], 16;" :: "r"(dst_smem), "l"(src));
}

__device__ __forceinline__ void issue_tile(const float* __restrict__ Kg,
                                           const float* __restrict__ Vg,
                                           float* Ks, float* Vs,
                                           int kt, int buf, int tid) {
    const float* kp = Kg + (size_t)kt * BK * D_;
    const float* vp = Vg + (size_t)kt * BK * D_;
    float* kdst = Ks + buf * BK * KSTRIDE;
    float* vdst = Vs + buf * BK * KSTRIDE;
    #pragma unroll
    for (int i = 0; i < 4; ++i) {
        int slot = tid + i * NTHREADS;     // 0..1023 (float4 slots)
        int key = slot >> 4;               // 0..63
        int d4  = slot & 15;               // 0..15
        uint32_t dk = (uint32_t)__cvta_generic_to_shared(kdst + key * KSTRIDE + d4 * 4);
        cp_async16(dk, kp + key * D_ + d4 * 4);
        uint32_t dv = (uint32_t)__cvta_generic_to_shared(vdst + key * KSTRIDE + d4 * 4);
        cp_async16(dv, vp + key * D_ + d4 * 4);
    }
    asm volatile("cp.async.commit_group;");
}

__global__ void __launch_bounds__(NTHREADS, 1)
fa_tf32_kernel(const float* __restrict__ Q, const float* __restrict__ K,
               const float* __restrict__ V, const float* __restrict__ scale_div,
               float* __restrict__ O)
{
    extern __shared__ float smem[];
    float* Ks = smem;
    float* Vs = Ks + KBUF_FLOATS;
    float* Ps = Vs + VBUF_FLOATS;

    const int tid  = threadIdx.x;
    const int w    = tid >> 5;
    const int lane = tid & 31;
    const int g    = lane >> 2;   // 0..7 (row group)
    const int tg   = lane & 3;    // 0..3

    const int b  = blockIdx.y;
    const int q0 = blockIdx.x * BQ;

    // fold 1/x5 and log2(e) into the score scale (exp -> exp2 domain)
    const float escale = (1.0f / scale_div[0]) * 1.44269504088896340736f;

    // ---- load Q fragments (fp32, split to tf32 hi/lo at use) ----
    const int rA = q0 + w * 16 + g;
    const int rB = rA + 8;
    const float* Qa = Q + ((size_t)b * SQ_ + rA) * D_;
    const float* Qb = Q + ((size_t)b * SQ_ + rB) * D_;
    float qreg[8][4];
    #pragma unroll
    for (int s = 0; s < 8; ++s) {
        qreg[s][0] = __ldg(Qa + 8 * s + tg);
        qreg[s][1] = __ldg(Qb + 8 * s + tg);
        qreg[s][2] = __ldg(Qa + 8 * s + tg + 4);
        qreg[s][3] = __ldg(Qb + 8 * s + tg + 4);
    }

    const float* Kg = K + (size_t)b * SK_ * D_;
    const float* Vg = V + (size_t)b * SK_ * D_;

    float o[8][4];
    #pragma unroll
    for (int nt = 0; nt < 8; ++nt)
        #pragma unroll
        for (int j = 0; j < 4; ++j) o[nt][j] = 0.0f;

    float mA = -INFINITY, mB = -INFINITY, lA = 0.0f, lB = 0.0f;

    issue_tile(Kg, Vg, Ks, Vs, 0, 0, tid);

    const int NT = SK_ / BK;   // 64
    float* Pw = Ps + w * 16 * PSTRIDE;

    for (int t = 0; t < NT; ++t) {
        const int buf = t & 1;
        if (t + 1 < NT) {
            issue_tile(Kg, Vg, Ks, Vs, t + 1, (t + 1) & 1, tid);
            asm volatile("cp.async.wait_group 1;");
        } else {
            asm volatile("cp.async.wait_group 0;");
        }
        __syncthreads();

        const float* Kt = Ks + buf * BK * KSTRIDE;
        const float* Vt = Vs + buf * BK * KSTRIDE;

        // ---- S = Q K^T via tf32x3 (hi*hi + hi*lo + lo*hi) ----
        float sc[8][4];
        #pragma unroll
        for (int nt = 0; nt < 8; ++nt)
            #pragma unroll
            for (int j = 0; j < 4; ++j) sc[nt][j] = 0.0f;

        #pragma unroll
        for (int s = 0; s < 8; ++s) {
            uint32_t ahi[4], alo[4];
            #pragma unroll
            for (int j = 0; j < 4; ++j) {
                float q = qreg[s][j];
                ahi[j] = f2tf32(q);
                alo[j] = f2tf32(q - __uint_as_float(ahi[j]));
            }
            #pragma unroll
            for (int nt = 0; nt < 8; ++nt) {
                float k0 = Kt[(nt * 8 + g) * KSTRIDE + 8 * s + tg];
                float k1 = Kt[(nt * 8 + g) * KSTRIDE + 8 * s + tg + 4];
                uint32_t bh0 = f2tf32(k0), bh1 = f2tf32(k1);
                uint32_t bl0 = f2tf32(k0 - __uint_as_float(bh0));
                uint32_t bl1 = f2tf32(k1 - __uint_as_float(bh1));
                mma_tf32(sc[nt][0], sc[nt][1], sc[nt][2], sc[nt][3],
                         ahi[0], ahi[1], ahi[2], ahi[3], bh0, bh1);
                mma_tf32(sc[nt][0], sc[nt][1], sc[nt][2], sc[nt][3],
                         ahi[0], ahi[1], ahi[2], ahi[3], bl0, bl1);
                mma_tf32(sc[nt][0], sc[nt][1], sc[nt][2], sc[nt][3],
                         alo[0], alo[1], alo[2], alo[3], bh0, bh1);
            }
        }

        // ---- online softmax (exp2 domain) ----
        float rmA = -INFINITY, rmB = -INFINITY;
        #pragma unroll
        for (int nt = 0; nt < 8; ++nt) {
            sc[nt][0] *= escale; sc[nt][1] *= escale;
            sc[nt][2] *= escale; sc[nt][3] *= escale;
            rmA = fmaxf(rmA, fmaxf(sc[nt][0], sc[nt][1]));
            rmB = fmaxf(rmB, fmaxf(sc[nt][2], sc[nt][3]));
        }
        rmA = fmaxf(rmA, __shfl_xor_sync(0xffffffffu, rmA, 1));
        rmA = fmaxf(rmA, __shfl_xor_sync(0xffffffffu, rmA, 2));
        rmB = fmaxf(rmB, __shfl_xor_sync(0xffffffffu, rmB, 1));
        rmB = fmaxf(rmB, __shfl_xor_sync(0xffffffffu, rmB, 2));

        const float mAn = fmaxf(mA, rmA);
        const float mBn = fmaxf(mB, rmB);
        const float aA = fast_exp2(mA - mAn);
        const float aB = fast_exp2(mB - mBn);
        mA = mAn; mB = mBn;
        lA *= aA;  lB *= aB;

        #pragma unroll
        for (int nt = 0; nt < 8; ++nt) {
            float p0 = fast_exp2(sc[nt][0] - mA);
            float p1 = fast_exp2(sc[nt][1] - mA);
            float p2 = fast_exp2(sc[nt][2] - mB);
            float p3 = fast_exp2(sc[nt][3] - mB);
            lA += p0 + p1;  lB += p2 + p3;
            o[nt][0] *= aA; o[nt][1] *= aA;
            o[nt][2] *= aB; o[nt][3] *= aB;
            // store P pre-rounded to tf32 bits (A-operand for PV)
            Pw[g * PSTRIDE + nt * 8 + 2 * tg]           = __uint_as_float(f2tf32(p0));
            Pw[g * PSTRIDE + nt * 8 + 2 * tg + 1]       = __uint_as_float(f2tf32(p1));
            Pw[(g + 8) * PSTRIDE + nt * 8 + 2 * tg]     = __uint_as_float(f2tf32(p2));
            Pw[(g + 8) * PSTRIDE + nt * 8 + 2 * tg + 1] = __uint_as_float(f2tf32(p3));
        }
        __syncwarp();

        // ---- O += P V (single-pass tf32) ----
        #pragma unroll
        for (int s = 0; s < 8; ++s) {
            uint32_t a0 = __float_as_uint(Pw[g * PSTRIDE + 8 * s + tg]);
            uint32_t a1 = __float_as_uint(Pw[(g + 8) * PSTRIDE + 8 * s + tg]);
            uint32_t a2 = __float_as_uint(Pw[g * PSTRIDE + 8 * s + tg + 4]);
            uint32_t a3 = __float_as_uint(Pw[(g + 8) * PSTRIDE + 8 * s + tg + 4]);
            #pragma unroll
            for (int nt = 0; nt < 8; ++nt) {
                uint32_t b0 = f2tf32(Vt[(8 * s + tg) * KSTRIDE + nt * 8 + g]);
                uint32_t b1 = f2tf32(Vt[(8 * s + tg + 4) * KSTRIDE + nt * 8 + g]);
                mma_tf32(o[nt][0], o[nt][1], o[nt][2], o[nt][3],
                         a0, a1, a2, a3, b0, b1);
            }
        }
        __syncwarp();
        __syncthreads();   // everyone done with this K/V buffer before it is refilled
    }

    // ---- epilogue: normalize and store ----
    lA += __shfl_xor_sync(0xffffffffu, lA, 1);
    lA += __shfl_xor_sync(0xffffffffu, lA, 2);
    lB += __shfl_xor_sync(0xffffffffu, lB, 1);
    lB += __shfl_xor_sync(0xffffffffu, lB, 2);
    const float iA = 1.0f / lA;
    const float iB = 1.0f / lB;

    float* Oa = O + ((size_t)b * SQ_ + rA) * D_;
    float* Ob = O + ((size_t)b * SQ_ + rB) * D_;
    #pragma unroll
    for (int nt = 0; nt < 8; ++nt) {
        float2 vA = make_float2(o[nt][0] * iA, o[nt][1] * iA);
        float2 vB = make_float2(o[nt][2] * iB, o[nt][3] * iB);
        *reinterpret_cast<float2*>(Oa + nt * 8 + 2 * tg) = vA;
        *reinterpret_cast<float2*>(Ob + nt * 8 + 2 * tg) = vB;
    }
}

extern "C" void kernel_launch(void* const* d_in, const int* in_sizes, int n_in,
                              void* d_out, int out_size) {
    const float* Q = (const float*)d_in[0];
    const float* K = (const float*)d_in[1];
    const float* V = (const float*)d_in[2];
    const float* s = (const float*)d_in[n_in - 1];   // x5 is the last input (x4 may or may not materialize)
    float* O = (float*)d_out;

    cudaFuncSetAttribute(fa_tf32_kernel,
                         cudaFuncAttributeMaxDynamicSharedMemorySize, SMEM_BYTES);
    dim3 grid(SQ_ / BQ, B_);
    fa_tf32_kernel<<<grid, NTHREADS, SMEM_BYTES>>>(Q, K, V, s, O);
}

// round 2
// speedup vs baseline: 1.1410x; 1.1410x over previous
#include <cuda_runtime.h>
#include <cstdint>
#include <math.h>

// Problem constants (fixed by the reference: B=8, SQ=SK=4096, D=64)
#define B_   8
#define SQ_  4096
#define SK_  4096
#define D_   64

// Tiling
#define BQ   128          // q rows per CTA
#define BK   64           // keys per tile
#define NWARP 8
#define NTHREADS 256
#define KSTRIDE   68      // raw K/V smem row stride (floats)
#define KHLSTRIDE 136     // interleaved (hi,lo) K plane row stride
#define VTSTRIDE  72      // transposed V plane row stride (dim-major)
#define PSTRIDE   68

#define KRAW_FLOATS (2 * BK * KSTRIDE)            // 8704
#define VRAW_FLOATS (2 * BK * KSTRIDE)            // 8704
#define KHL_FLOATS  (BK * KHLSTRIDE)              // 8704
#define VT_FLOATS   (D_ * VTSTRIDE)               // 4608
#define PBUF_FLOATS (NWARP * 16 * PSTRIDE)        // 8704
#define SMEM_FLOATS (KRAW_FLOATS + VRAW_FLOATS + KHL_FLOATS + VT_FLOATS + PBUF_FLOATS)
#define SMEM_BYTES  (SMEM_FLOATS * 4)             // 157696

__device__ __forceinline__ uint32_t f2tf32(float f) {
    uint32_t u;
    asm("cvt.rna.tf32.f32 %0, %1;" : "=r"(u) : "f"(f));
    return u;
}

__device__ __forceinline__ float fast_exp2(float x) {
    float y;
    asm("ex2.approx.ftz.f32 %0, %1;" : "=f"(y) : "f"(x));
    return y;
}

// truncate to tf32 (low 13 mantissa bits dropped) — matches what the MMA
// hardware reads, so storing this value and summing it keeps P/V-normalization
// exactly consistent (bias cancels in the l-division).
__device__ __forceinline__ float trunc_tf32(float f) {
    return __uint_as_float(__float_as_uint(f) & 0xffffe000u);
}

__device__ __forceinline__ void mma_tf32(float& d0, float& d1, float& d2, float& d3,
                                         uint32_t a0, uint32_t a1, uint32_t a2, uint32_t a3,
                                         uint32_t b0, uint32_t b1) {
    asm volatile(
        "mma.sync.aligned.m16n8k8.row.col.f32.tf32.tf32.f32 "
        "{%0,%1,%2,%3}, {%4,%5,%6,%7}, {%8,%9}, {%0,%1,%2,%3};"
        : "+f"(d0), "+f"(d1), "+f"(d2), "+f"(d3)
        : "r"(a0), "r"(a1), "r"(a2), "r"(a3), "r"(b0), "r"(b1));
}

__device__ __forceinline__ void cp_async16(uint32_t dst_smem, const void* src) {
    asm volatile("cp.async.cg.shared.global [%0], [%1], 16;" :: "r"(dst_smem), "l"(src));
}

__device__ __forceinline__ void issue_tile(const float* __restrict__ Kg,
                                           const float* __restrict__ Vg,
                                           float* Kraw, float* Vraw,
                                           int kt, int buf, int tid) {
    const float* kp = Kg + (size_t)kt * BK * D_;
    const float* vp = Vg + (size_t)kt * BK * D_;
    float* kdst = Kraw + buf * BK * KSTRIDE;
    float* vdst = Vraw + buf * BK * KSTRIDE;
    #pragma unroll
    for (int i = 0; i < 4; ++i) {
        int slot = tid + i * NTHREADS;     // 0..1023 (float4 slots)
        int key = slot >> 4;               // 0..63
        int d4  = slot & 15;               // 0..15
        uint32_t dk = (uint32_t)__cvta_generic_to_shared(kdst + key * KSTRIDE + d4 * 4);
        cp_async16(dk, kp + key * D_ + d4 * 4);
        uint32_t dv = (uint32_t)__cvta_generic_to_shared(vdst + key * KSTRIDE + d4 * 4);
        cp_async16(dv, vp + key * D_ + d4 * 4);
    }
    asm volatile("cp.async.commit_group;");
}

__global__ void __launch_bounds__(NTHREADS, 1)
fa_tf32_kernel(const float* __restrict__ Q, const float* __restrict__ K,
               const float* __restrict__ V, const float* __restrict__ scale_div,
               float* __restrict__ O)
{
    extern __shared__ float smem[];
    float* Kraw = smem;
    float* Vraw = Kraw + KRAW_FLOATS;
    float* Khl  = Vraw + VRAW_FLOATS;    // [key][2*dim]   interleaved (hi,lo)
    float* Vt   = Khl  + KHL_FLOATS;     // [dim][kappa(key)]  rna tf32
    float* Ps   = Vt   + VT_FLOATS;

    const int tid  = threadIdx.x;
    const int w    = tid >> 5;
    const int lane = tid & 31;
    const int g    = lane >> 2;   // 0..7
    const int tg   = lane & 3;    // 0..3

    const int b  = blockIdx.y;
    const int q0 = blockIdx.x * BQ;

    // fold 1/x5 and log2(e) into the score scale (exp -> exp2 domain)
    const float escale = (1.0f / scale_div[0]) * 1.44269504088896340736f;

    // ---- Q fragments: split to tf32 hi/lo ONCE (hoisted out of tile loop) ----
    const int rA = q0 + w * 16 + g;
    const int rB = rA + 8;
    const float* Qa = Q + ((size_t)b * SQ_ + rA) * D_;
    const float* Qb = Q + ((size_t)b * SQ_ + rB) * D_;
    uint32_t qhi[8][4], qlo[8][4];
    #pragma unroll
    for (int s = 0; s < 8; ++s) {
        float q_[4];
        q_[0] = __ldg(Qa + 8 * s + tg);
        q_[1] = __ldg(Qb + 8 * s + tg);
        q_[2] = __ldg(Qa + 8 * s + tg + 4);
        q_[3] = __ldg(Qb + 8 * s + tg + 4);
        #pragma unroll
        for (int j = 0; j < 4; ++j) {
            qhi[s][j] = f2tf32(q_[j]);
            // residual fed raw; MMA truncates it (error ~2^-21, negligible)
            qlo[s][j] = __float_as_uint(q_[j] - __uint_as_float(qhi[s][j]));
        }
    }

    const float* Kg = K + (size_t)b * SK_ * D_;
    const float* Vg = V + (size_t)b * SK_ * D_;

    float o[8][4];
    #pragma unroll
    for (int nt = 0; nt < 8; ++nt)
        #pragma unroll
        for (int j = 0; j < 4; ++j) o[nt][j] = 0.0f;

    float mA = -INFINITY, mB = -INFINITY, lA = 0.0f, lB = 0.0f;

    issue_tile(Kg, Vg, Kraw, Vraw, 0, 0, tid);

    const int NT = SK_ / BK;   // 64
    float* Pw = Ps + w * 16 * PSTRIDE;

    // per-thread convert-pass assignment: key = tid&63, dim chunk = tid>>6
    const int ckey = tid & 63;
    const int cdc  = tid >> 6;                 // 0..3 -> dims 16*cdc..16*cdc+15
    const int kcol = (ckey & 56) | ((ckey & 3) << 1) | ((ckey >> 2) & 1); // kappa

    for (int t = 0; t < NT; ++t) {
        const int buf = t & 1;
        if (t + 1 < NT) {
            issue_tile(Kg, Vg, Kraw, Vraw, t + 1, (t + 1) & 1, tid);
            asm volatile("cp.async.wait_group 1;");
        } else {
            asm volatile("cp.async.wait_group 0;");
        }
        __syncthreads();   // raw[t] visible; previous compute done with planes

        // ---- cooperative convert pass: raw -> Khl (hi,lo) and Vt (tf32, transposed) ----
        {
            const float* ksrc = Kraw + buf * BK * KSTRIDE + ckey * KSTRIDE + cdc * 16;
            float*       kdst = Khl + ckey * KHLSTRIDE + cdc * 32;
            #pragma unroll
            for (int i = 0; i < 4; ++i) {
                float4 v = *reinterpret_cast<const float4*>(ksrc + 4 * i);
                float h0 = __uint_as_float(f2tf32(v.x));
                float h1 = __uint_as_float(f2tf32(v.y));
                float h2 = __uint_as_float(f2tf32(v.z));
                float h3 = __uint_as_float(f2tf32(v.w));
                float4 o0 = make_float4(h0, v.x - h0, h1, v.y - h1);
                float4 o1 = make_float4(h2, v.z - h2, h3, v.w - h3);
                *reinterpret_cast<float4*>(kdst + 8 * i)     = o0;
                *reinterpret_cast<float4*>(kdst + 8 * i + 4) = o1;
            }
            const float* vsrc = Vraw + buf * BK * KSTRIDE + ckey * KSTRIDE + cdc * 16;
            #pragma unroll
            for (int i = 0; i < 4; ++i) {
                float4 v = *reinterpret_cast<const float4*>(vsrc + 4 * i);
                int d0 = cdc * 16 + 4 * i;
                Vt[(d0 + 0) * VTSTRIDE + kcol] = __uint_as_float(f2tf32(v.x));
                Vt[(d0 + 1) * VTSTRIDE + kcol] = __uint_as_float(f2tf32(v.y));
                Vt[(d0 + 2) * VTSTRIDE + kcol] = __uint_as_float(f2tf32(v.z));
                Vt[(d0 + 3) * VTSTRIDE + kcol] = __uint_as_float(f2tf32(v.w));
            }
        }
        __syncthreads();   // planes ready

        // ---- S = Q K^T via tf32x3 (hi*hi + hi*lo + lo*hi) ----
        float sc[8][4];
        #pragma unroll
        for (int nt = 0; nt < 8; ++nt)
            #pragma unroll
            for (int j = 0; j < 4; ++j) sc[nt][j] = 0.0f;

        #pragma unroll
        for (int s = 0; s < 8; ++s) {
            #pragma unroll
            for (int nt = 0; nt < 8; ++nt) {
                const float* krow = Khl + (nt * 8 + g) * KHLSTRIDE;
                float2 b0 = *reinterpret_cast<const float2*>(krow + 2 * (8 * s + tg));
                float2 b1 = *reinterpret_cast<const float2*>(krow + 2 * (8 * s + tg + 4));
                uint32_t bh0 = __float_as_uint(b0.x), bl0 = __float_as_uint(b0.y);
                uint32_t bh1 = __float_as_uint(b1.x), bl1 = __float_as_uint(b1.y);
                mma_tf32(sc[nt][0], sc[nt][1], sc[nt][2], sc[nt][3],
                         qhi[s][0], qhi[s][1], qhi[s][2], qhi[s][3], bh0, bh1);
                mma_tf32(sc[nt][0], sc[nt][1], sc[nt][2], sc[nt][3],
                         qhi[s][0], qhi[s][1], qhi[s][2], qhi[s][3], bl0, bl1);
                mma_tf32(sc[nt][0], sc[nt][1], sc[nt][2], sc[nt][3],
                         qlo[s][0], qlo[s][1], qlo[s][2], qlo[s][3], bh0, bh1);
            }
        }

        // ---- online softmax: max on RAW scores, scale folded into exp2 FFMA ----
        float rmA = -INFINITY, rmB = -INFINITY;
        #pragma unroll
        for (int nt = 0; nt < 8; ++nt) {
            rmA = fmaxf(rmA, fmaxf(sc[nt][0], sc[nt][1]));
            rmB = fmaxf(rmB, fmaxf(sc[nt][2], sc[nt][3]));
        }
        rmA = fmaxf(rmA, __shfl_xor_sync(0xffffffffu, rmA, 1));
        rmA = fmaxf(rmA, __shfl_xor_sync(0xffffffffu, rmA, 2));
        rmB = fmaxf(rmB, __shfl_xor_sync(0xffffffffu, rmB, 1));
        rmB = fmaxf(rmB, __shfl_xor_sync(0xffffffffu, rmB, 2));

        const float mAn = fmaxf(mA, rmA * escale);
        const float mBn = fmaxf(mB, rmB * escale);
        const float aA = fast_exp2(mA - mAn);
        const float aB = fast_exp2(mB - mBn);
        mA = mAn; mB = mBn;
        lA *= aA;  lB *= aB;

        #pragma unroll
        for (int nt = 0; nt < 8; ++nt) {
            float p0 = trunc_tf32(fast_exp2(fmaf(sc[nt][0], escale, -mA)));
            float p1 = trunc_tf32(fast_exp2(fmaf(sc[nt][1], escale, -mA)));
            float p2 = trunc_tf32(fast_exp2(fmaf(sc[nt][2], escale, -mB)));
            float p3 = trunc_tf32(fast_exp2(fmaf(sc[nt][3], escale, -mB)));
            lA += p0 + p1;  lB += p2 + p3;
            o[nt][0] *= aA; o[nt][1] *= aA;
            o[nt][2] *= aB; o[nt][3] *= aB;
            *reinterpret_cast<float2*>(Pw + g * PSTRIDE + nt * 8 + 2 * tg)
                = make_float2(p0, p1);
            *reinterpret_cast<float2*>(Pw + (g + 8) * PSTRIDE + nt * 8 + 2 * tg)
                = make_float2(p2, p3);
        }
        __syncwarp();

        // ---- O += P V (single-pass tf32; V pre-rounded, P truncated+consistent) ----
        #pragma unroll
        for (int s = 0; s < 8; ++s) {
            uint32_t a0 = __float_as_uint(Pw[g * PSTRIDE + 8 * s + tg]);
            uint32_t a1 = __float_as_uint(Pw[(g + 8) * PSTRIDE + 8 * s + tg]);
            uint32_t a2 = __float_as_uint(Pw[g * PSTRIDE + 8 * s + tg + 4]);
            uint32_t a3 = __float_as_uint(Pw[(g + 8) * PSTRIDE + 8 * s + tg + 4]);
            #pragma unroll
            for (int nt = 0; nt < 8; ++nt) {
                float2 bv = *reinterpret_cast<const float2*>(
                    Vt + (nt * 8 + g) * VTSTRIDE + 8 * s + 2 * tg);
                mma_tf32(o[nt][0], o[nt][1], o[nt][2], o[nt][3],
                         a0, a1, a2, a3,
                         __float_as_uint(bv.x), __float_as_uint(bv.y));
            }
        }
        __syncwarp();
        __syncthreads();   // everyone done with planes before next convert pass
    }

    // ---- epilogue: normalize and store ----
    lA += __shfl_xor_sync(0xffffffffu, lA, 1);
    lA += __shfl_xor_sync(0xffffffffu, lA, 2);
    lB += __shfl_xor_sync(0xffffffffu, lB, 1);
    lB += __shfl_xor_sync(0xffffffffu, lB, 2);
    const float iA = 1.0f / lA;
    const float iB = 1.0f / lB;

    float* Oa = O + ((size_t)b * SQ_ + rA) * D_;
    float* Ob = O + ((size_t)b * SQ_ + rB) * D_;
    #pragma unroll
    for (int nt = 0; nt < 8; ++nt) {
        float2 vA = make_float2(o[nt][0] * iA, o[nt][1] * iA);
        float2 vB = make_float2(o[nt][2] * iB, o[nt][3] * iB);
        *reinterpret_cast<float2*>(Oa + nt * 8 + 2 * tg) = vA;
        *reinterpret_cast<float2*>(Ob + nt * 8 + 2 * tg) = vB;
    }
}

extern "C" void kernel_launch(void* const* d_in, const int* in_sizes, int n_in,
                              void* d_out, int out_size) {
    const float* Q = (const float*)d_in[0];
    const float* K = (const float*)d_in[1];
    const float* V = (const float*)d_in[2];
    const float* s = (const float*)d_in[n_in - 1];   // x5 is the last input
    float* O = (float*)d_out;

    cudaFuncSetAttribute(fa_tf32_kernel,
                         cudaFuncAttributeMaxDynamicSharedMemorySize, SMEM_BYTES);
    dim3 grid(SQ_ / BQ, B_);
    fa_tf32_kernel<<<grid, NTHREADS, SMEM_BYTES>>>(Q, K, V, s, O);
}